// round 3
// baseline (speedup 1.0000x reference)
#include <cuda_runtime.h>
#include <math_constants.h>

// ---------------------------------------------------------------------------
// Problem constants
// ---------------------------------------------------------------------------
#define BB    4
#define NN    8192
#define DD    1024
#define NHEAD 8
#define DH    64
#define HID   512        // NHEAD*DH
#define WIN   128
#define NWIN  (NN / WIN) // 64
#define NQSEL 1024
#define NKVSEL 2048

// ---------------------------------------------------------------------------
// Device scratch (static __device__ arrays; allocation-free per harness rules)
// ---------------------------------------------------------------------------
__device__ float g_xn  [BB * NN * DD];          // rmsnorm(x) light
__device__ float g_ql  [BB * NN * HID];         // light q
__device__ float g_kvl [BB * NN * 2 * HID];     // light kv
__device__ float g_aol [BB * NN * HID];         // light attn out (pre-Wo)
__device__ float g_s   [2 * BB * NN];           // routing scores: [q | kv]
__device__ int   g_qmap [BB * NQSEL];           // selected q -> global row in x
__device__ int   g_kvmap[BB * NKVSEL];          // selected kv -> global row in x
__device__ float g_xq  [BB * NQSEL * DD];       // gathered+normed q tokens
__device__ float g_ctx [BB * NKVSEL * DD];      // gathered+normed kv tokens
__device__ float g_qh  [BB * NQSEL * HID];      // heavy q
__device__ float g_kvh [BB * NKVSEL * 2 * HID]; // heavy kv (k|v interleaved per head)
__device__ float g_oh  [BB * NQSEL * HID];      // heavy attn out (pre-Wo)

// ---------------------------------------------------------------------------
// RMSNorm: y = x / max(||x||,1e-12) * sqrt(D) * gamma     (one block per row)
// ---------------------------------------------------------------------------
__global__ void rmsnorm_kernel(const float* __restrict__ x,
                               const float* __restrict__ gamma,
                               float* __restrict__ y)
{
    int row = blockIdx.x;
    const float* xr = x + (size_t)row * DD;
    float* yr = y + (size_t)row * DD;
    __shared__ float red[256];
    int tid = threadIdx.x;
    float ss = 0.f;
    for (int d = tid; d < DD; d += 256) { float v = xr[d]; ss += v * v; }
    red[tid] = ss; __syncthreads();
    for (int o = 128; o > 0; o >>= 1) {
        if (tid < o) red[tid] += red[tid + o];
        __syncthreads();
    }
    float inv = 32.0f / fmaxf(sqrtf(red[0]), 1e-12f);
    for (int d = tid; d < DD; d += 256) yr[d] = xr[d] * inv * gamma[d];
}

// gather selected rows of x and rmsnorm them (heavy path)
__global__ void gather_norm_kernel(const float* __restrict__ x,
                                   const float* __restrict__ gamma)
{
    int r = blockIdx.x;
    const float* xr;
    float* yr;
    if (r < BB * NQSEL) {
        xr = x + (size_t)g_qmap[r] * DD;
        yr = g_xq + (size_t)r * DD;
    } else {
        int rr = r - BB * NQSEL;
        xr = x + (size_t)g_kvmap[rr] * DD;
        yr = g_ctx + (size_t)rr * DD;
    }
    __shared__ float red[256];
    int tid = threadIdx.x;
    float ss = 0.f;
    for (int d = tid; d < DD; d += 256) { float v = xr[d]; ss += v * v; }
    red[tid] = ss; __syncthreads();
    for (int o = 128; o > 0; o >>= 1) {
        if (tid < o) red[tid] += red[tid + o];
        __syncthreads();
    }
    float inv = 32.0f / fmaxf(sqrtf(red[0]), 1e-12f);
    for (int d = tid; d < DD; d += 256) yr[d] = xr[d] * inv * gamma[d];
}

// ---------------------------------------------------------------------------
// SGEMM: C[M,N] = A[M,K] @ B      128x128 block tile, BK=8, 8x8 per thread
//  BKN    : B stored [K,N] row-major (true)  or [N,K] row-major (false, B^T)
//  INDEXED: epilogue does C[rowmap[m]] += acc  (heavy scatter-accumulate)
// ---------------------------------------------------------------------------
template<bool BKN, bool INDEXED>
__global__ __launch_bounds__(256)
void sgemm_kernel(const float* __restrict__ A, const float* __restrict__ Bm,
                  float* __restrict__ C, int M, int N, int K,
                  const int* __restrict__ rowmap)
{
    __shared__ float As[8][128];
    __shared__ float Bs[8][128];
    int tid = threadIdx.x;
    int bm = blockIdx.y * 128;
    int bn = blockIdx.x * 128;
    int tx = tid & 15, ty = tid >> 4;
    float acc[8][8];
    #pragma unroll
    for (int i = 0; i < 8; i++)
        #pragma unroll
        for (int j = 0; j < 8; j++) acc[i][j] = 0.f;

    int aRow = tid >> 1, aCol = (tid & 1) * 4;

    for (int k0 = 0; k0 < K; k0 += 8) {
        float4 av = *(const float4*)(A + (size_t)(bm + aRow) * K + k0 + aCol);
        As[aCol + 0][aRow] = av.x; As[aCol + 1][aRow] = av.y;
        As[aCol + 2][aRow] = av.z; As[aCol + 3][aRow] = av.w;
        if (BKN) {
            int bRow = tid >> 5, bCol = (tid & 31) * 4;
            float4 bv = *(const float4*)(Bm + (size_t)(k0 + bRow) * N + bn + bCol);
            *(float4*)&Bs[bRow][bCol] = bv;
        } else {
            int bRow = tid >> 1, bCol = (tid & 1) * 4;
            float4 bv = *(const float4*)(Bm + (size_t)(bn + bRow) * K + k0 + bCol);
            Bs[bCol + 0][bRow] = bv.x; Bs[bCol + 1][bRow] = bv.y;
            Bs[bCol + 2][bRow] = bv.z; Bs[bCol + 3][bRow] = bv.w;
        }
        __syncthreads();
        #pragma unroll
        for (int kk = 0; kk < 8; kk++) {
            float ar[8], br[8];
            #pragma unroll
            for (int i = 0; i < 8; i++) ar[i] = As[kk][ty * 8 + i];
            #pragma unroll
            for (int j = 0; j < 8; j++) br[j] = Bs[kk][tx * 8 + j];
            #pragma unroll
            for (int i = 0; i < 8; i++)
                #pragma unroll
                for (int j = 0; j < 8; j++)
                    acc[i][j] += ar[i] * br[j];
        }
        __syncthreads();
    }

    #pragma unroll
    for (int i = 0; i < 8; i++) {
        int row = bm + ty * 8 + i;
        if (INDEXED) {
            int grow = rowmap[row];
            float* cp = C + (size_t)grow * N + bn + tx * 8;
            #pragma unroll
            for (int j = 0; j < 8; j++) cp[j] += acc[i][j];
        } else {
            float* cp = C + (size_t)row * N + bn + tx * 8;
            *(float4*)cp       = make_float4(acc[i][0], acc[i][1], acc[i][2], acc[i][3]);
            *(float4*)(cp + 4) = make_float4(acc[i][4], acc[i][5], acc[i][6], acc[i][7]);
        }
    }
}

// ---------------------------------------------------------------------------
// Routing scores: s_q[b,n] = x[b,n,:].q_tok ; s_kv likewise (1 warp per token)
// ---------------------------------------------------------------------------
__global__ void route_score_kernel(const float* __restrict__ x,
                                   const float* __restrict__ qt,
                                   const float* __restrict__ kt,
                                   float* __restrict__ s)
{
    int gw = (blockIdx.x * blockDim.x + threadIdx.x) >> 5;
    int lane = threadIdx.x & 31;
    if (gw >= BB * NN) return;
    const float* xr = x + (size_t)gw * DD;
    float sq = 0.f, sk = 0.f;
    for (int d = lane; d < DD; d += 32) {
        float v = xr[d];
        sq += v * qt[d];
        sk += v * kt[d];
    }
    #pragma unroll
    for (int o = 16; o > 0; o >>= 1) {
        sq += __shfl_down_sync(0xffffffffu, sq, o);
        sk += __shfl_down_sync(0xffffffffu, sk, o);
    }
    if (lane == 0) { s[gw] = sq; s[BB * NN + gw] = sk; }
}

// ---------------------------------------------------------------------------
// Coordinate-descent relaxed top-k + exact stable top-k selection.
// blocks 0..3: q route per batch ; blocks 4..7: kv route per batch.
// b_t = -relu(s + a_t)  =>  s + b_t = min(s, -a_t): the 50-iteration descent
// iterates only the scalar a per batch. Final score = exp(min(s + a, 0));
// selection replicates jax.lax.top_k stable ordering via
// key = (score_bits << 13) | (8191 - idx) and a 45-bit radix select.
// ---------------------------------------------------------------------------
__global__ void route_select_kernel(const float* __restrict__ sAll)
{
    __shared__ float ss[NN];
    __shared__ float redf[256];
    __shared__ int   redi[256];
    __shared__ int   ctr;

    int r = blockIdx.x;
    bool isQ = (r < 4);
    int b = isQ ? r : r - 4;
    const float* s = sAll + (isQ ? 0 : BB * NN) + (size_t)b * NN;
    float ksoft = isQ ? 1152.0f : 2304.0f;   // num_tokens * 9/8
    int ksel = isQ ? NQSEL : NKVSEL;
    int tid = threadIdx.x;

    for (int i = tid; i < NN; i += 256) ss[i] = s[i];
    if (tid == 0) ctr = 0;
    __syncthreads();

    // --- 50 iterations of coordinate descent (scalar a per batch) ---
    float a = 0.0f;
    float logk = logf(ksoft);
    for (int it = 0; it < 50; it++) {
        float na = -a;
        float m = -CUDART_INF_F;
        for (int i = tid; i < NN; i += 256) {
            float v = (it == 0) ? 0.0f : fminf(ss[i], na);
            m = fmaxf(m, v);
        }
        redf[tid] = m; __syncthreads();
        for (int o = 128; o > 0; o >>= 1) {
            if (tid < o) redf[tid] = fmaxf(redf[tid], redf[tid + o]);
            __syncthreads();
        }
        float M = redf[0]; __syncthreads();
        float sum = 0.f;
        for (int i = tid; i < NN; i += 256) {
            float v = (it == 0) ? 0.0f : fminf(ss[i], na);
            sum += expf(v - M);
        }
        redf[tid] = sum; __syncthreads();
        for (int o = 128; o > 0; o >>= 1) {
            if (tid < o) redf[tid] += redf[tid + o];
            __syncthreads();
        }
        float S = redf[0]; __syncthreads();
        a = logk - (M + logf(S));
    }

    // --- overwrite ss with final scores = exp(min(s+a, 0)) ---
    for (int i = tid; i < NN; i += 256)
        ss[i] = expf(fminf(ss[i] + a, 0.0f));
    __syncthreads();

    // --- radix select: threshold P = ksel-th largest 45-bit key ---
    unsigned long long P = 0;
    int desired = ksel;
    for (int bit = 44; bit >= 0; bit--) {
        unsigned long long want = (P >> bit) | 1ull;
        int c = 0;
        for (int i = tid; i < NN; i += 256) {
            unsigned long long key =
                ((unsigned long long)__float_as_uint(ss[i]) << 13) |
                (unsigned long long)(8191 - i);
            c += (int)((key >> bit) == want);
        }
        redi[tid] = c; __syncthreads();
        for (int o = 128; o > 0; o >>= 1) {
            if (tid < o) redi[tid] += redi[tid + o];
            __syncthreads();
        }
        int cnt = redi[0]; __syncthreads();
        if (cnt >= desired) P |= (1ull << bit);
        else desired -= cnt;
    }

    // --- emit selected global rows (order irrelevant; set semantics) ---
    for (int i = tid; i < NN; i += 256) {
        unsigned long long key =
            ((unsigned long long)__float_as_uint(ss[i]) << 13) |
            (unsigned long long)(8191 - i);
        if (key >= P) {
            int pos = atomicAdd(&ctr, 1);
            int grow = b * NN + i;
            if (isQ) g_qmap[b * NQSEL + pos] = grow;
            else     g_kvmap[b * NKVSEL + pos] = grow;
        }
    }
}

// ---------------------------------------------------------------------------
// Attention (shared flash-style core). One block per (b, tile-of-128-q, head);
// 128 threads, one query row per thread. KV staged through 64-row static-smem
// chunks (32 KB total). K rows are read warp-broadcast from smem.
//   Q/O rows at qrow0 + r, columns qOff..qOff+63, row stride HID
//   KV  rows at kvrow0 + r, k col kOff, v col kOff+vDelta, row stride 2*HID
// ---------------------------------------------------------------------------
template<int NKV_TILES>
__device__ __forceinline__
void attn_core(const float* __restrict__ Q, const float* __restrict__ KV,
               float* __restrict__ O,
               int qrow0, int kvrow0, int qOff, int kOff, int vDelta)
{
    __shared__ float Ks[64][DH];
    __shared__ float Vs[64][DH];
    int tid = threadIdx.x;

    // load own q row (16 float4 = 64 floats, per-thread contiguous), scale
    float q[DH];
    {
        const float4* qp = (const float4*)(Q + (size_t)(qrow0 + tid) * HID + qOff);
        #pragma unroll
        for (int i = 0; i < DH / 4; i++) {
            float4 v = qp[i];
            q[4 * i + 0] = v.x * 0.125f; q[4 * i + 1] = v.y * 0.125f;
            q[4 * i + 2] = v.z * 0.125f; q[4 * i + 3] = v.w * 0.125f;
        }
    }

    float m = -CUDART_INF_F, l = 0.f, acc[DH];
    #pragma unroll
    for (int d = 0; d < DH; d++) acc[d] = 0.f;

    for (int t = 0; t < NKV_TILES; t++) {
        __syncthreads();
        int kvbase = kvrow0 + t * 64;
        // 128 threads stage 64 rows x 64 cols of K and V
        for (int i = tid; i < 64 * DH; i += 128) {
            int rr = i >> 6, d = i & 63;
            size_t base = (size_t)(kvbase + rr) * (2 * HID) + kOff + d;
            Ks[rr][d] = KV[base];
            Vs[rr][d] = KV[base + vDelta];
        }
        __syncthreads();

        for (int j0 = 0; j0 < 64; j0 += 16) {
            float sv[16];
            float cm = m;
            #pragma unroll
            for (int jj = 0; jj < 16; jj++) {
                const float* kr = Ks[j0 + jj];
                float dot = 0.f;
                #pragma unroll
                for (int d = 0; d < DH; d++) dot += q[d] * kr[d];
                sv[jj] = dot;
                cm = fmaxf(cm, dot);
            }
            float sc = expf(m - cm);
            m = cm; l *= sc;
            #pragma unroll
            for (int d = 0; d < DH; d++) acc[d] *= sc;
            #pragma unroll
            for (int jj = 0; jj < 16; jj++) {
                float p = expf(sv[jj] - m);
                l += p;
                const float* vr = Vs[j0 + jj];
                #pragma unroll
                for (int d = 0; d < DH; d++) acc[d] += p * vr[d];
            }
        }
    }
    float inv = 1.f / l;
    float4* op = (float4*)(O + (size_t)(qrow0 + tid) * HID + qOff);
    #pragma unroll
    for (int i = 0; i < DH / 4; i++)
        op[i] = make_float4(acc[4 * i + 0] * inv, acc[4 * i + 1] * inv,
                            acc[4 * i + 2] * inv, acc[4 * i + 3] * inv);
}

// light: window of 128 == the q tile; Q col h*DH; KV k at h*DH, v at +HID
__global__ __launch_bounds__(128)
void light_attn_kernel(const float* __restrict__ Q, const float* __restrict__ KV,
                       float* __restrict__ O)
{
    int id = blockIdx.x;
    int h = id & 7;
    int w = (id >> 3) & (NWIN - 1);
    int b = id >> 9;
    int rowbase = b * NN + w * WIN;
    attn_core<WIN / 64>(Q, KV, O, rowbase, rowbase, h * DH, h * DH, HID);
}

// heavy: q tiles of 128 over NQSEL, full NKVSEL context; Q col h*DH;
// kv row has per-head [k(64) | v(64)] pairs: k at h*128, v at +64
__global__ __launch_bounds__(128)
void heavy_attn_kernel(const float* __restrict__ QH, const float* __restrict__ KVH,
                       float* __restrict__ OH)
{
    int id = blockIdx.x;
    int qt = id & 7;
    int h = (id >> 3) & 7;
    int b = id >> 6;
    int qbase = b * NQSEL + qt * 128;
    attn_core<NKVSEL / 64>(QH, KVH, OH, qbase, b * NKVSEL,
                           h * DH, h * (2 * DH), DH);
}

// ---------------------------------------------------------------------------
// launch
// ---------------------------------------------------------------------------
extern "C" void kernel_launch(void* const* d_in, const int* in_sizes, int n_in,
                              void* d_out, int out_size)
{
    const float* x           = (const float*)d_in[0];
    const float* gamma_light = (const float*)d_in[1];
    const float* wq_light    = (const float*)d_in[2];
    const float* wkv_light   = (const float*)d_in[3];
    const float* wo_light    = (const float*)d_in[4];
    const float* q_tok       = (const float*)d_in[5];
    const float* kv_tok      = (const float*)d_in[6];
    const float* gamma_heavy = (const float*)d_in[7];
    const float* wq_heavy    = (const float*)d_in[8];
    const float* wkv_heavy   = (const float*)d_in[9];
    const float* wo_heavy    = (const float*)d_in[10];
    float* out = (float*)d_out;

    float *p_xn, *p_ql, *p_kvl, *p_aol, *p_s, *p_xq, *p_ctx, *p_qh, *p_kvh, *p_oh;
    int *p_qmap;
    cudaGetSymbolAddress((void**)&p_xn,  g_xn);
    cudaGetSymbolAddress((void**)&p_ql,  g_ql);
    cudaGetSymbolAddress((void**)&p_kvl, g_kvl);
    cudaGetSymbolAddress((void**)&p_aol, g_aol);
    cudaGetSymbolAddress((void**)&p_s,   g_s);
    cudaGetSymbolAddress((void**)&p_xq,  g_xq);
    cudaGetSymbolAddress((void**)&p_ctx, g_ctx);
    cudaGetSymbolAddress((void**)&p_qh,  g_qh);
    cudaGetSymbolAddress((void**)&p_kvh, g_kvh);
    cudaGetSymbolAddress((void**)&p_oh,  g_oh);
    cudaGetSymbolAddress((void**)&p_qmap, g_qmap);

    // ---- light path ----
    rmsnorm_kernel<<<BB * NN, 256>>>(x, gamma_light, p_xn);
    sgemm_kernel<true, false><<<dim3(HID / 128, BB * NN / 128), 256>>>(
        p_xn, wq_light, p_ql, BB * NN, HID, DD, nullptr);
    sgemm_kernel<true, false><<<dim3(2 * HID / 128, BB * NN / 128), 256>>>(
        p_xn, wkv_light, p_kvl, BB * NN, 2 * HID, DD, nullptr);
    light_attn_kernel<<<BB * NWIN * NHEAD, 128>>>(p_ql, p_kvl, p_aol);
    sgemm_kernel<true, false><<<dim3(DD / 128, BB * NN / 128), 256>>>(
        p_aol, wo_light, out, BB * NN, DD, HID, nullptr);

    // ---- routing ----
    route_score_kernel<<<(BB * NN * 32) / 256, 256>>>(x, q_tok, kv_tok, p_s);
    route_select_kernel<<<8, 256>>>(p_s);

    // ---- heavy path ----
    gather_norm_kernel<<<BB * NQSEL + BB * NKVSEL, 256>>>(x, gamma_heavy);
    sgemm_kernel<true, false><<<dim3(HID / 128, BB * NQSEL / 128), 256>>>(
        p_xq, wq_heavy, p_qh, BB * NQSEL, HID, DD, nullptr);
    sgemm_kernel<false, false><<<dim3(2 * HID / 128, BB * NKVSEL / 128), 256>>>(
        p_ctx, wkv_heavy, p_kvh, BB * NKVSEL, 2 * HID, DD, nullptr);
    heavy_attn_kernel<<<BB * NHEAD * (NQSEL / 128), 128>>>(p_qh, p_kvh, p_oh);
    sgemm_kernel<true, true><<<dim3(DD / 128, BB * NQSEL / 128), 256>>>(
        p_oh, wo_heavy, out, BB * NQSEL, DD, HID, p_qmap);
}

// round 4
// speedup vs baseline: 1.1562x; 1.1562x over previous
#include <cuda_runtime.h>
#include <cuda_bf16.h>
#include <math_constants.h>

// ---------------------------------------------------------------------------
// Problem constants
// ---------------------------------------------------------------------------
#define BB    4
#define NN    8192
#define DD    1024
#define NHEAD 8
#define DH    64
#define HID   512        // NHEAD*DH
#define WIN   128
#define NWIN  (NN / WIN) // 64
#define NQSEL 1024
#define NKVSEL 2048

// ---------------------------------------------------------------------------
// Device scratch
// ---------------------------------------------------------------------------
__device__ float g_xn  [BB * NN * DD];
__device__ float g_ql  [BB * NN * HID];
__device__ float g_kvl [BB * NN * 2 * HID];
__device__ float g_aol [BB * NN * HID];
__device__ float g_s   [2 * BB * NN];
__device__ int   g_qmap [BB * NQSEL];
__device__ int   g_kvmap[BB * NKVSEL];
__device__ float g_xq  [BB * NQSEL * DD];
__device__ float g_ctx [BB * NKVSEL * DD];
__device__ float g_qh  [BB * NQSEL * HID];
__device__ float g_kvh [BB * NKVSEL * 2 * HID];
__device__ float g_oh  [BB * NQSEL * HID];

// ---------------------------------------------------------------------------
// RMSNorm
// ---------------------------------------------------------------------------
__global__ void rmsnorm_kernel(const float* __restrict__ x,
                               const float* __restrict__ gamma,
                               float* __restrict__ y)
{
    int row = blockIdx.x;
    const float* xr = x + (size_t)row * DD;
    float* yr = y + (size_t)row * DD;
    __shared__ float red[256];
    int tid = threadIdx.x;
    float ss = 0.f;
    for (int d = tid; d < DD; d += 256) { float v = xr[d]; ss += v * v; }
    red[tid] = ss; __syncthreads();
    for (int o = 128; o > 0; o >>= 1) {
        if (tid < o) red[tid] += red[tid + o];
        __syncthreads();
    }
    float inv = 32.0f / fmaxf(sqrtf(red[0]), 1e-12f);
    for (int d = tid; d < DD; d += 256) yr[d] = xr[d] * inv * gamma[d];
}

__global__ void gather_norm_kernel(const float* __restrict__ x,
                                   const float* __restrict__ gamma)
{
    int r = blockIdx.x;
    const float* xr;
    float* yr;
    if (r < BB * NQSEL) {
        xr = x + (size_t)g_qmap[r] * DD;
        yr = g_xq + (size_t)r * DD;
    } else {
        int rr = r - BB * NQSEL;
        xr = x + (size_t)g_kvmap[rr] * DD;
        yr = g_ctx + (size_t)rr * DD;
    }
    __shared__ float red[256];
    int tid = threadIdx.x;
    float ss = 0.f;
    for (int d = tid; d < DD; d += 256) { float v = xr[d]; ss += v * v; }
    red[tid] = ss; __syncthreads();
    for (int o = 128; o > 0; o >>= 1) {
        if (tid < o) red[tid] += red[tid + o];
        __syncthreads();
    }
    float inv = 32.0f / fmaxf(sqrtf(red[0]), 1e-12f);
    for (int d = tid; d < DD; d += 256) yr[d] = xr[d] * inv * gamma[d];
}

// ---------------------------------------------------------------------------
// Tensor-core GEMM (split-bf16, fp32 accumulate): C = A @ B
//   A fp32 [M,K] row-major; split on the fly into bf16 hi/lo.
//   BKN=true : B fp32 [K,N] row-major;  BKN=false: B fp32 [N,K] (B^T)
//   INDEXED  : C[rowmap[m], :] += acc   else C[m, :] = acc
// Block: 128x128x32, 256 threads (8 warps: 4 m x 2 n), warp tile 32x64,
// mma.sync.m16n8k16 bf16, products hi*hi + hi*lo + lo*hi.
// ---------------------------------------------------------------------------
#define MMA_BF16(d, a, b0, b1)                                                  \
    asm volatile(                                                               \
        "mma.sync.aligned.m16n8k16.row.col.f32.bf16.bf16.f32 "                  \
        "{%0,%1,%2,%3}, {%4,%5,%6,%7}, {%8,%9}, {%0,%1,%2,%3};"                 \
        : "+f"((d)[0]), "+f"((d)[1]), "+f"((d)[2]), "+f"((d)[3])                \
        : "r"((a)[0]), "r"((a)[1]), "r"((a)[2]), "r"((a)[3]),                   \
          "r"(b0), "r"(b1))

template<bool BKN, bool INDEXED>
__global__ __launch_bounds__(256)
void bgemm_kernel(const float* __restrict__ A, const float* __restrict__ Bm,
                  float* __restrict__ C, int M, int N, int K,
                  const int* __restrict__ rowmap)
{
    __shared__ __nv_bfloat16 Ahi[128][36];
    __shared__ __nv_bfloat16 Alo[128][36];
    __shared__ __nv_bfloat16 Bhi[128][36];
    __shared__ __nv_bfloat16 Blo[128][36];

    int tid = threadIdx.x;
    int lane = tid & 31, warp = tid >> 5;
    int wm = warp >> 1, wn = warp & 1;
    int bm = blockIdx.y * 128, bn = blockIdx.x * 128;
    int g  = lane >> 2;          // 0..7
    int qp = (lane & 3) * 2;     // 0,2,4,6

    float acc[2][8][4];
    #pragma unroll
    for (int mt = 0; mt < 2; mt++)
        #pragma unroll
        for (int nt = 0; nt < 8; nt++)
            #pragma unroll
            for (int i = 0; i < 4; i++) acc[mt][nt][i] = 0.f;

    for (int k0 = 0; k0 < K; k0 += 32) {
        // ---- stage A: 128 rows x 32 cols fp32, split hi/lo ----
        {
            int row = tid >> 1;
            int cb = (tid & 1) * 16;
            const float4* src = (const float4*)(A + (size_t)(bm + row) * K + k0 + cb);
            #pragma unroll
            for (int i = 0; i < 4; i++) {
                float4 v = src[i];
                float vv[4] = {v.x, v.y, v.z, v.w};
                #pragma unroll
                for (int j = 0; j < 4; j++) {
                    __nv_bfloat16 h = __float2bfloat16(vv[j]);
                    Ahi[row][cb + i * 4 + j] = h;
                    Alo[row][cb + i * 4 + j] =
                        __float2bfloat16(vv[j] - __bfloat162float(h));
                }
            }
        }
        // ---- stage B into [n][k] layout ----
        if (BKN) {
            int kr = tid >> 3;          // 0..31
            int nb = (tid & 7) * 16;    // 0..112
            const float4* src = (const float4*)(Bm + (size_t)(k0 + kr) * N + bn + nb);
            #pragma unroll
            for (int i = 0; i < 4; i++) {
                float4 v = src[i];
                float vv[4] = {v.x, v.y, v.z, v.w};
                #pragma unroll
                for (int j = 0; j < 4; j++) {
                    __nv_bfloat16 h = __float2bfloat16(vv[j]);
                    Bhi[nb + i * 4 + j][kr] = h;
                    Blo[nb + i * 4 + j][kr] =
                        __float2bfloat16(vv[j] - __bfloat162float(h));
                }
            }
        } else {
            int n = tid >> 1;
            int cb = (tid & 1) * 16;
            const float4* src = (const float4*)(Bm + (size_t)(bn + n) * K + k0 + cb);
            #pragma unroll
            for (int i = 0; i < 4; i++) {
                float4 v = src[i];
                float vv[4] = {v.x, v.y, v.z, v.w};
                #pragma unroll
                for (int j = 0; j < 4; j++) {
                    __nv_bfloat16 h = __float2bfloat16(vv[j]);
                    Bhi[n][cb + i * 4 + j] = h;
                    Blo[n][cb + i * 4 + j] =
                        __float2bfloat16(vv[j] - __bfloat162float(h));
                }
            }
        }
        __syncthreads();

        #pragma unroll
        for (int kk = 0; kk < 32; kk += 16) {
            // A fragments (m16k16): R0 row g, R1 row g+8, R2 row g k+8, R3 row g+8 k+8
            unsigned ah[2][4], al[2][4];
            #pragma unroll
            for (int mt = 0; mt < 2; mt++) {
                int r0 = wm * 32 + mt * 16 + g;
                ah[mt][0] = *(const unsigned*)&Ahi[r0    ][kk + qp];
                ah[mt][1] = *(const unsigned*)&Ahi[r0 + 8][kk + qp];
                ah[mt][2] = *(const unsigned*)&Ahi[r0    ][kk + 8 + qp];
                ah[mt][3] = *(const unsigned*)&Ahi[r0 + 8][kk + 8 + qp];
                al[mt][0] = *(const unsigned*)&Alo[r0    ][kk + qp];
                al[mt][1] = *(const unsigned*)&Alo[r0 + 8][kk + qp];
                al[mt][2] = *(const unsigned*)&Alo[r0    ][kk + 8 + qp];
                al[mt][3] = *(const unsigned*)&Alo[r0 + 8][kk + 8 + qp];
            }
            #pragma unroll
            for (int nt = 0; nt < 8; nt++) {
                int c0 = wn * 64 + nt * 8 + g;
                unsigned bh0 = *(const unsigned*)&Bhi[c0][kk + qp];
                unsigned bh1 = *(const unsigned*)&Bhi[c0][kk + 8 + qp];
                unsigned bl0 = *(const unsigned*)&Blo[c0][kk + qp];
                unsigned bl1 = *(const unsigned*)&Blo[c0][kk + 8 + qp];
                #pragma unroll
                for (int mt = 0; mt < 2; mt++) {
                    MMA_BF16(acc[mt][nt], ah[mt], bh0, bh1);
                    MMA_BF16(acc[mt][nt], ah[mt], bl0, bl1);
                    MMA_BF16(acc[mt][nt], al[mt], bh0, bh1);
                }
            }
        }
        __syncthreads();
    }

    // ---- epilogue ----
    #pragma unroll
    for (int mt = 0; mt < 2; mt++) {
        int row0 = bm + wm * 32 + mt * 16 + g;
        #pragma unroll
        for (int nt = 0; nt < 8; nt++) {
            int col = bn + wn * 64 + nt * 8 + qp;
            if (INDEXED) {
                int gr0 = rowmap[row0];
                int gr1 = rowmap[row0 + 8];
                float* p0 = C + (size_t)gr0 * N + col;
                float* p1 = C + (size_t)gr1 * N + col;
                p0[0] += acc[mt][nt][0]; p0[1] += acc[mt][nt][1];
                p1[0] += acc[mt][nt][2]; p1[1] += acc[mt][nt][3];
            } else {
                *(float2*)(C + (size_t)row0 * N + col) =
                    make_float2(acc[mt][nt][0], acc[mt][nt][1]);
                *(float2*)(C + (size_t)(row0 + 8) * N + col) =
                    make_float2(acc[mt][nt][2], acc[mt][nt][3]);
            }
        }
    }
}

// ---------------------------------------------------------------------------
// Routing scores
// ---------------------------------------------------------------------------
__global__ void route_score_kernel(const float* __restrict__ x,
                                   const float* __restrict__ qt,
                                   const float* __restrict__ kt,
                                   float* __restrict__ s)
{
    int gw = (blockIdx.x * blockDim.x + threadIdx.x) >> 5;
    int lane = threadIdx.x & 31;
    if (gw >= BB * NN) return;
    const float* xr = x + (size_t)gw * DD;
    float sq = 0.f, sk = 0.f;
    for (int d = lane; d < DD; d += 32) {
        float v = xr[d];
        sq += v * qt[d];
        sk += v * kt[d];
    }
    #pragma unroll
    for (int o = 16; o > 0; o >>= 1) {
        sq += __shfl_down_sync(0xffffffffu, sq, o);
        sk += __shfl_down_sync(0xffffffffu, sk, o);
    }
    if (lane == 0) { s[gw] = sq; s[BB * NN + gw] = sk; }
}

// ---------------------------------------------------------------------------
// Coordinate-descent relaxed top-k + exact stable top-k selection.
// ---------------------------------------------------------------------------
__global__ void route_select_kernel(const float* __restrict__ sAll)
{
    __shared__ float ss[NN];
    __shared__ float redf[256];
    __shared__ int   redi[256];
    __shared__ int   ctr;

    int r = blockIdx.x;
    bool isQ = (r < 4);
    int b = isQ ? r : r - 4;
    const float* s = sAll + (isQ ? 0 : BB * NN) + (size_t)b * NN;
    float ksoft = isQ ? 1152.0f : 2304.0f;
    int ksel = isQ ? NQSEL : NKVSEL;
    int tid = threadIdx.x;

    for (int i = tid; i < NN; i += 256) ss[i] = s[i];
    if (tid == 0) ctr = 0;
    __syncthreads();

    float a = 0.0f;
    float logk = logf(ksoft);
    for (int it = 0; it < 50; it++) {
        float na = -a;
        float m = -CUDART_INF_F;
        for (int i = tid; i < NN; i += 256) {
            float v = (it == 0) ? 0.0f : fminf(ss[i], na);
            m = fmaxf(m, v);
        }
        redf[tid] = m; __syncthreads();
        for (int o = 128; o > 0; o >>= 1) {
            if (tid < o) redf[tid] = fmaxf(redf[tid], redf[tid + o]);
            __syncthreads();
        }
        float M = redf[0]; __syncthreads();
        float sum = 0.f;
        for (int i = tid; i < NN; i += 256) {
            float v = (it == 0) ? 0.0f : fminf(ss[i], na);
            sum += expf(v - M);
        }
        redf[tid] = sum; __syncthreads();
        for (int o = 128; o > 0; o >>= 1) {
            if (tid < o) redf[tid] += redf[tid + o];
            __syncthreads();
        }
        float S = redf[0]; __syncthreads();
        a = logk - (M + logf(S));
    }

    for (int i = tid; i < NN; i += 256)
        ss[i] = expf(fminf(ss[i] + a, 0.0f));
    __syncthreads();

    unsigned long long P = 0;
    int desired = ksel;
    for (int bit = 44; bit >= 0; bit--) {
        unsigned long long want = (P >> bit) | 1ull;
        int c = 0;
        for (int i = tid; i < NN; i += 256) {
            unsigned long long key =
                ((unsigned long long)__float_as_uint(ss[i]) << 13) |
                (unsigned long long)(8191 - i);
            c += (int)((key >> bit) == want);
        }
        redi[tid] = c; __syncthreads();
        for (int o = 128; o > 0; o >>= 1) {
            if (tid < o) redi[tid] += redi[tid + o];
            __syncthreads();
        }
        int cnt = redi[0]; __syncthreads();
        if (cnt >= desired) P |= (1ull << bit);
        else desired -= cnt;
    }

    for (int i = tid; i < NN; i += 256) {
        unsigned long long key =
            ((unsigned long long)__float_as_uint(ss[i]) << 13) |
            (unsigned long long)(8191 - i);
        if (key >= P) {
            int pos = atomicAdd(&ctr, 1);
            int grow = b * NN + i;
            if (isQ) g_qmap[b * NQSEL + pos] = grow;
            else     g_kvmap[b * NKVSEL + pos] = grow;
        }
    }
}

// ---------------------------------------------------------------------------
// Attention (flash-style), unchanged from R3
// ---------------------------------------------------------------------------
template<int NKV_TILES>
__device__ __forceinline__
void attn_core(const float* __restrict__ Q, const float* __restrict__ KV,
               float* __restrict__ O,
               int qrow0, int kvrow0, int qOff, int kOff, int vDelta)
{
    __shared__ float Ks[64][DH];
    __shared__ float Vs[64][DH];
    int tid = threadIdx.x;

    float q[DH];
    {
        const float4* qp = (const float4*)(Q + (size_t)(qrow0 + tid) * HID + qOff);
        #pragma unroll
        for (int i = 0; i < DH / 4; i++) {
            float4 v = qp[i];
            q[4 * i + 0] = v.x * 0.125f; q[4 * i + 1] = v.y * 0.125f;
            q[4 * i + 2] = v.z * 0.125f; q[4 * i + 3] = v.w * 0.125f;
        }
    }

    float m = -CUDART_INF_F, l = 0.f, acc[DH];
    #pragma unroll
    for (int d = 0; d < DH; d++) acc[d] = 0.f;

    for (int t = 0; t < NKV_TILES; t++) {
        __syncthreads();
        int kvbase = kvrow0 + t * 64;
        for (int i = tid; i < 64 * DH; i += 128) {
            int rr = i >> 6, d = i & 63;
            size_t base = (size_t)(kvbase + rr) * (2 * HID) + kOff + d;
            Ks[rr][d] = KV[base];
            Vs[rr][d] = KV[base + vDelta];
        }
        __syncthreads();

        for (int j0 = 0; j0 < 64; j0 += 16) {
            float sv[16];
            float cm = m;
            #pragma unroll
            for (int jj = 0; jj < 16; jj++) {
                const float* kr = Ks[j0 + jj];
                float dot = 0.f;
                #pragma unroll
                for (int d = 0; d < DH; d++) dot += q[d] * kr[d];
                sv[jj] = dot;
                cm = fmaxf(cm, dot);
            }
            float sc = expf(m - cm);
            m = cm; l *= sc;
            #pragma unroll
            for (int d = 0; d < DH; d++) acc[d] *= sc;
            #pragma unroll
            for (int jj = 0; jj < 16; jj++) {
                float p = expf(sv[jj] - m);
                l += p;
                const float* vr = Vs[j0 + jj];
                #pragma unroll
                for (int d = 0; d < DH; d++) acc[d] += p * vr[d];
            }
        }
    }
    float inv = 1.f / l;
    float4* op = (float4*)(O + (size_t)(qrow0 + tid) * HID + qOff);
    #pragma unroll
    for (int i = 0; i < DH / 4; i++)
        op[i] = make_float4(acc[4 * i + 0] * inv, acc[4 * i + 1] * inv,
                            acc[4 * i + 2] * inv, acc[4 * i + 3] * inv);
}

__global__ __launch_bounds__(128)
void light_attn_kernel(const float* __restrict__ Q, const float* __restrict__ KV,
                       float* __restrict__ O)
{
    int id = blockIdx.x;
    int h = id & 7;
    int w = (id >> 3) & (NWIN - 1);
    int b = id >> 9;
    int rowbase = b * NN + w * WIN;
    attn_core<WIN / 64>(Q, KV, O, rowbase, rowbase, h * DH, h * DH, HID);
}

__global__ __launch_bounds__(128)
void heavy_attn_kernel(const float* __restrict__ QH, const float* __restrict__ KVH,
                       float* __restrict__ OH)
{
    int id = blockIdx.x;
    int qt = id & 7;
    int h = (id >> 3) & 7;
    int b = id >> 6;
    int qbase = b * NQSEL + qt * 128;
    attn_core<NKVSEL / 64>(QH, KVH, OH, qbase, b * NKVSEL,
                           h * DH, h * (2 * DH), DH);
}

// ---------------------------------------------------------------------------
// launch
// ---------------------------------------------------------------------------
extern "C" void kernel_launch(void* const* d_in, const int* in_sizes, int n_in,
                              void* d_out, int out_size)
{
    const float* x           = (const float*)d_in[0];
    const float* gamma_light = (const float*)d_in[1];
    const float* wq_light    = (const float*)d_in[2];
    const float* wkv_light   = (const float*)d_in[3];
    const float* wo_light    = (const float*)d_in[4];
    const float* q_tok       = (const float*)d_in[5];
    const float* kv_tok      = (const float*)d_in[6];
    const float* gamma_heavy = (const float*)d_in[7];
    const float* wq_heavy    = (const float*)d_in[8];
    const float* wkv_heavy   = (const float*)d_in[9];
    const float* wo_heavy    = (const float*)d_in[10];
    float* out = (float*)d_out;

    float *p_xn, *p_ql, *p_kvl, *p_aol, *p_s, *p_xq, *p_ctx, *p_qh, *p_kvh, *p_oh;
    int *p_qmap;
    cudaGetSymbolAddress((void**)&p_xn,  g_xn);
    cudaGetSymbolAddress((void**)&p_ql,  g_ql);
    cudaGetSymbolAddress((void**)&p_kvl, g_kvl);
    cudaGetSymbolAddress((void**)&p_aol, g_aol);
    cudaGetSymbolAddress((void**)&p_s,   g_s);
    cudaGetSymbolAddress((void**)&p_xq,  g_xq);
    cudaGetSymbolAddress((void**)&p_ctx, g_ctx);
    cudaGetSymbolAddress((void**)&p_qh,  g_qh);
    cudaGetSymbolAddress((void**)&p_kvh, g_kvh);
    cudaGetSymbolAddress((void**)&p_oh,  g_oh);
    cudaGetSymbolAddress((void**)&p_qmap, g_qmap);

    // ---- light path ----
    rmsnorm_kernel<<<BB * NN, 256>>>(x, gamma_light, p_xn);
    bgemm_kernel<true, false><<<dim3(HID / 128, BB * NN / 128), 256>>>(
        p_xn, wq_light, p_ql, BB * NN, HID, DD, nullptr);
    bgemm_kernel<true, false><<<dim3(2 * HID / 128, BB * NN / 128), 256>>>(
        p_xn, wkv_light, p_kvl, BB * NN, 2 * HID, DD, nullptr);
    light_attn_kernel<<<BB * NWIN * NHEAD, 128>>>(p_ql, p_kvl, p_aol);
    bgemm_kernel<true, false><<<dim3(DD / 128, BB * NN / 128), 256>>>(
        p_aol, wo_light, out, BB * NN, DD, HID, nullptr);

    // ---- routing ----
    route_score_kernel<<<(BB * NN * 32) / 256, 256>>>(x, q_tok, kv_tok, p_s);
    route_select_kernel<<<8, 256>>>(p_s);

    // ---- heavy path ----
    gather_norm_kernel<<<BB * NQSEL + BB * NKVSEL, 256>>>(x, gamma_heavy);
    bgemm_kernel<true, false><<<dim3(HID / 128, BB * NQSEL / 128), 256>>>(
        p_xq, wq_heavy, p_qh, BB * NQSEL, HID, DD, nullptr);
    bgemm_kernel<false, false><<<dim3(2 * HID / 128, BB * NKVSEL / 128), 256>>>(
        p_ctx, wkv_heavy, p_kvh, BB * NKVSEL, 2 * HID, DD, nullptr);
    heavy_attn_kernel<<<BB * NHEAD * (NQSEL / 128), 128>>>(p_qh, p_kvh, p_oh);
    bgemm_kernel<true, true><<<dim3(DD / 128, BB * NQSEL / 128), 256>>>(
        p_oh, wo_heavy, out, BB * NQSEL, DD, HID, p_qmap);
}